// round 3
// baseline (speedup 1.0000x reference)
#include <cuda_runtime.h>
#include <math.h>

// Problem constants
// B=4, S=1024, D=1024, H=16, DH=64  -> BH = 64 heads, per-head Q/K/V = [1024,64] contiguous
#define M_QKV   4096          // B*S
#define DIM     1024
#define NHEADS  64            // B*H
#define SEQ     1024
#define HDIM    64
#define SCALE   0.03125f      // D^-0.5 = 1/32
#define LN_EPS  1e-5f

// -------------------- scratch (allocation-free: __device__ globals) --------------------
__device__ float g_q[M_QKV * DIM];
__device__ float g_k[M_QKV * DIM];
__device__ float g_v[M_QKV * DIM];
__device__ float g_ctx[M_QKV * DIM];
__device__ float g_attn[(size_t)NHEADS * SEQ * SEQ];   // fallback if attn not in d_out

// ============================================================================
// Kernel 1: QKV projections.  C[m,n] = sum_k A[m,k]*W[n,k] + b[n]
// 128x128 tile, BK=8, 256 threads, 8x8 micro-tile per thread.
// blockIdx.z selects q/k/v.
// ============================================================================
__global__ __launch_bounds__(256)
void qkv_kernel(const float* __restrict__ Xq, const float* __restrict__ Xk, const float* __restrict__ Xv,
                const float* __restrict__ Wq, const float* __restrict__ Wk, const float* __restrict__ Wv,
                const float* __restrict__ bq, const float* __restrict__ bk, const float* __restrict__ bv)
{
    __shared__ float As[8][132];   // [k][m], padded (132*4B = 16B-aligned rows, conflict-free)
    __shared__ float Bs[8][132];   // [k][n]

    const int z = blockIdx.z;
    const float* A    = (z == 0) ? Xq : (z == 1) ? Xk : Xv;
    const float* W    = (z == 0) ? Wq : (z == 1) ? Wk : Wv;
    const float* bias = (z == 0) ? bq : (z == 1) ? bk : bv;
    float*       C    = (z == 0) ? g_q : (z == 1) ? g_k : g_v;

    const int tid = threadIdx.x;
    const int m0  = blockIdx.y * 128;
    const int n0  = blockIdx.x * 128;
    const int tx  = tid & 15;       // 16 cols of 8
    const int ty  = tid >> 4;       // 16 rows of 8
    const int lrow = tid >> 1;      // 0..127
    const int lcol = (tid & 1) * 4; // 0 or 4

    const float* Ap = A + (size_t)(m0 + lrow) * DIM + lcol;
    const float* Wp = W + (size_t)(n0 + lrow) * DIM + lcol;

    float acc[8][8];
#pragma unroll
    for (int i = 0; i < 8; i++)
#pragma unroll
        for (int j = 0; j < 8; j++) acc[i][j] = 0.f;

    for (int k0 = 0; k0 < DIM; k0 += 8) {
        float4 a4 = *(const float4*)(Ap + k0);
        float4 w4 = *(const float4*)(Wp + k0);
        As[lcol + 0][lrow] = a4.x; As[lcol + 1][lrow] = a4.y;
        As[lcol + 2][lrow] = a4.z; As[lcol + 3][lrow] = a4.w;
        Bs[lcol + 0][lrow] = w4.x; Bs[lcol + 1][lrow] = w4.y;
        Bs[lcol + 2][lrow] = w4.z; Bs[lcol + 3][lrow] = w4.w;
        __syncthreads();
#pragma unroll
        for (int kk = 0; kk < 8; kk++) {
            float ra[8], rb[8];
            *(float4*)(ra)     = *(const float4*)&As[kk][ty * 8];
            *(float4*)(ra + 4) = *(const float4*)&As[kk][ty * 8 + 4];
            *(float4*)(rb)     = *(const float4*)&Bs[kk][tx * 8];
            *(float4*)(rb + 4) = *(const float4*)&Bs[kk][tx * 8 + 4];
#pragma unroll
            for (int i = 0; i < 8; i++)
#pragma unroll
                for (int j = 0; j < 8; j++)
                    acc[i][j] = fmaf(ra[i], rb[j], acc[i][j]);
        }
        __syncthreads();
    }

#pragma unroll
    for (int i = 0; i < 8; i++) {
        const int row = m0 + ty * 8 + i;
        const int col = n0 + tx * 8;
        float4 o0, o1;
        o0.x = acc[i][0] + bias[col + 0];
        o0.y = acc[i][1] + bias[col + 1];
        o0.z = acc[i][2] + bias[col + 2];
        o0.w = acc[i][3] + bias[col + 3];
        o1.x = acc[i][4] + bias[col + 4];
        o1.y = acc[i][5] + bias[col + 5];
        o1.z = acc[i][6] + bias[col + 6];
        o1.w = acc[i][7] + bias[col + 7];
        *(float4*)&C[(size_t)row * DIM + col]     = o0;
        *(float4*)&C[(size_t)row * DIM + col + 4] = o1;
    }
}

// ============================================================================
// Kernel 2: per-head scores  S[bh][i][j] = scale * sum_d Q[i,d]*K[j,d]
// Same tiling as above with lda=ldb=64, K=64.  Writes scaled logits to attn.
// ============================================================================
__global__ __launch_bounds__(256)
void scores_kernel(float* attn_ext)
{
    float* attn = attn_ext ? attn_ext : g_attn;

    __shared__ float As[8][132];
    __shared__ float Bs[8][132];

    const int bh = blockIdx.z;
    const float* Q = g_q + (size_t)bh * SEQ * HDIM;
    const float* K = g_k + (size_t)bh * SEQ * HDIM;
    float*       C = attn + (size_t)bh * SEQ * SEQ;

    const int tid  = threadIdx.x;
    const int m0   = blockIdx.y * 128;
    const int n0   = blockIdx.x * 128;
    const int tx   = tid & 15;
    const int ty   = tid >> 4;
    const int lrow = tid >> 1;
    const int lcol = (tid & 1) * 4;

    const float* Qp = Q + (size_t)(m0 + lrow) * HDIM + lcol;
    const float* Kp = K + (size_t)(n0 + lrow) * HDIM + lcol;

    float acc[8][8];
#pragma unroll
    for (int i = 0; i < 8; i++)
#pragma unroll
        for (int j = 0; j < 8; j++) acc[i][j] = 0.f;

    for (int k0 = 0; k0 < HDIM; k0 += 8) {
        float4 a4 = *(const float4*)(Qp + k0);
        float4 w4 = *(const float4*)(Kp + k0);
        As[lcol + 0][lrow] = a4.x; As[lcol + 1][lrow] = a4.y;
        As[lcol + 2][lrow] = a4.z; As[lcol + 3][lrow] = a4.w;
        Bs[lcol + 0][lrow] = w4.x; Bs[lcol + 1][lrow] = w4.y;
        Bs[lcol + 2][lrow] = w4.z; Bs[lcol + 3][lrow] = w4.w;
        __syncthreads();
#pragma unroll
        for (int kk = 0; kk < 8; kk++) {
            float ra[8], rb[8];
            *(float4*)(ra)     = *(const float4*)&As[kk][ty * 8];
            *(float4*)(ra + 4) = *(const float4*)&As[kk][ty * 8 + 4];
            *(float4*)(rb)     = *(const float4*)&Bs[kk][tx * 8];
            *(float4*)(rb + 4) = *(const float4*)&Bs[kk][tx * 8 + 4];
#pragma unroll
            for (int i = 0; i < 8; i++)
#pragma unroll
                for (int j = 0; j < 8; j++)
                    acc[i][j] = fmaf(ra[i], rb[j], acc[i][j]);
        }
        __syncthreads();
    }

#pragma unroll
    for (int i = 0; i < 8; i++) {
        const int row = m0 + ty * 8 + i;
        const int col = n0 + tx * 8;
        float4 o0, o1;
        o0.x = acc[i][0] * SCALE; o0.y = acc[i][1] * SCALE;
        o0.z = acc[i][2] * SCALE; o0.w = acc[i][3] * SCALE;
        o1.x = acc[i][4] * SCALE; o1.y = acc[i][5] * SCALE;
        o1.z = acc[i][6] * SCALE; o1.w = acc[i][7] * SCALE;
        *(float4*)&C[(size_t)row * SEQ + col]     = o0;
        *(float4*)&C[(size_t)row * SEQ + col + 4] = o1;
    }
}

// ============================================================================
// Kernel 3: row softmax, in place.  One block (256 thr) per row of 1024.
// Row lives entirely in registers (4 floats/thread); single read + write.
// ============================================================================
__global__ __launch_bounds__(256)
void softmax_kernel(float* attn_ext)
{
    float* attn = attn_ext ? attn_ext : g_attn;
    float* row  = attn + (size_t)blockIdx.x * SEQ;
    const int t = threadIdx.x;

    float4 v = *(const float4*)&row[t * 4];

    __shared__ float red[256];
    float lmax = fmaxf(fmaxf(v.x, v.y), fmaxf(v.z, v.w));
    red[t] = lmax;
    __syncthreads();
#pragma unroll
    for (int s = 128; s > 0; s >>= 1) {
        if (t < s) red[t] = fmaxf(red[t], red[t + s]);
        __syncthreads();
    }
    const float mx = red[0];
    __syncthreads();

    float e0 = expf(v.x - mx), e1 = expf(v.y - mx);
    float e2 = expf(v.z - mx), e3 = expf(v.w - mx);
    red[t] = e0 + e1 + e2 + e3;
    __syncthreads();
#pragma unroll
    for (int s = 128; s > 0; s >>= 1) {
        if (t < s) red[t] += red[t + s];
        __syncthreads();
    }
    const float inv = 1.0f / red[0];

    float4 o = make_float4(e0 * inv, e1 * inv, e2 * inv, e3 * inv);
    *(float4*)&row[t * 4] = o;
}

// ============================================================================
// Kernel 4: context = P @ V per head.  M=1024, N=64, K=1024.
// 128x64 tile, BK=16, 256 threads, 8x4 micro-tile per thread.
// ============================================================================
__global__ __launch_bounds__(256)
void pv_kernel(const float* attn_ext_c)
{
    const float* attn = attn_ext_c ? attn_ext_c : g_attn;

    __shared__ float Ps[16][132];  // [k][m] transposed
    __shared__ float Vs[16][68];   // [k][n]

    const int bh = blockIdx.z;
    const float* P = attn + (size_t)bh * SEQ * SEQ;
    const float* V = g_v  + (size_t)bh * SEQ * HDIM;
    float*       C = g_ctx + (size_t)bh * SEQ * HDIM;

    const int tid = threadIdx.x;
    const int m0  = blockIdx.y * 128;
    const int tx  = tid & 15;   // n-group: tx*4 (0..60)
    const int ty  = tid >> 4;   // m-group: ty*8 (0..120)

    // P loader: 128 rows x 16 cols = 512 float4, 2 per thread
    const int pr = tid >> 1;        // 0..127
    const int pc = (tid & 1) * 8;   // 0 or 8
    // V loader: 16 rows x 64 cols = 256 float4, 1 per thread
    const int vr = tid >> 4;        // 0..15
    const int vc = (tid & 15) * 4;  // 0..60

    float acc[8][4];
#pragma unroll
    for (int i = 0; i < 8; i++)
#pragma unroll
        for (int j = 0; j < 4; j++) acc[i][j] = 0.f;

    for (int k0 = 0; k0 < SEQ; k0 += 16) {
        float4 p0 = *(const float4*)&P[(size_t)(m0 + pr) * SEQ + k0 + pc];
        float4 p1 = *(const float4*)&P[(size_t)(m0 + pr) * SEQ + k0 + pc + 4];
        Ps[pc + 0][pr] = p0.x; Ps[pc + 1][pr] = p0.y;
        Ps[pc + 2][pr] = p0.z; Ps[pc + 3][pr] = p0.w;
        Ps[pc + 4][pr] = p1.x; Ps[pc + 5][pr] = p1.y;
        Ps[pc + 6][pr] = p1.z; Ps[pc + 7][pr] = p1.w;
        *(float4*)&Vs[vr][vc] = *(const float4*)&V[(size_t)(k0 + vr) * HDIM + vc];
        __syncthreads();
#pragma unroll
        for (int kk = 0; kk < 16; kk++) {
            float ra[8], rb[4];
            *(float4*)(ra)     = *(const float4*)&Ps[kk][ty * 8];
            *(float4*)(ra + 4) = *(const float4*)&Ps[kk][ty * 8 + 4];
            *(float4*)(rb)     = *(const float4*)&Vs[kk][tx * 4];
#pragma unroll
            for (int i = 0; i < 8; i++)
#pragma unroll
                for (int j = 0; j < 4; j++)
                    acc[i][j] = fmaf(ra[i], rb[j], acc[i][j]);
        }
        __syncthreads();
    }

#pragma unroll
    for (int i = 0; i < 8; i++) {
        const int row = m0 + ty * 8 + i;
        float4 o = make_float4(acc[i][0], acc[i][1], acc[i][2], acc[i][3]);
        *(float4*)&C[(size_t)row * HDIM + tx * 4] = o;
    }
}

// ============================================================================
// Kernel 5: output = LayerNorm(query + context) * gamma + beta
// One block (256 thr) per row of 1024. (g_ctx flat == context[B,S,D] flat.)
// ============================================================================
__global__ __launch_bounds__(256)
void ln_kernel(const float* __restrict__ query, const float* __restrict__ gamma,
               const float* __restrict__ beta, float* __restrict__ out)
{
    const int row = blockIdx.x;
    const int t   = threadIdx.x;
    const float* qp = query + (size_t)row * DIM;
    const float* cp = g_ctx + (size_t)row * DIM;

    float4 qv = *(const float4*)&qp[t * 4];
    float4 cv = *(const float4*)&cp[t * 4];
    float x0 = qv.x + cv.x, x1 = qv.y + cv.y, x2 = qv.z + cv.z, x3 = qv.w + cv.w;

    __shared__ float red[256];
    red[t] = x0 + x1 + x2 + x3;
    __syncthreads();
#pragma unroll
    for (int s = 128; s > 0; s >>= 1) {
        if (t < s) red[t] += red[t + s];
        __syncthreads();
    }
    const float mu = red[0] * (1.0f / (float)DIM);
    __syncthreads();

    float d0 = x0 - mu, d1 = x1 - mu, d2 = x2 - mu, d3 = x3 - mu;
    red[t] = d0 * d0 + d1 * d1 + d2 * d2 + d3 * d3;
    __syncthreads();
#pragma unroll
    for (int s = 128; s > 0; s >>= 1) {
        if (t < s) red[t] += red[t + s];
        __syncthreads();
    }
    const float rs = rsqrtf(red[0] * (1.0f / (float)DIM) + LN_EPS);

    float4 g4 = *(const float4*)&gamma[t * 4];
    float4 b4 = *(const float4*)&beta[t * 4];
    float4 o  = make_float4(d0 * rs * g4.x + b4.x,
                            d1 * rs * g4.y + b4.y,
                            d2 * rs * g4.z + b4.z,
                            d3 * rs * g4.w + b4.w);
    *(float4*)&out[(size_t)row * DIM + t * 4] = o;
}

// ============================================================================
// Launcher. Inputs (metadata order): key, value, query, Wq, bq, Wk, bk, Wv, bv,
// gamma, beta.  Output tuple: (output[B,S,D], attn[B*H,S,S]) concatenated.
// ============================================================================
extern "C" void kernel_launch(void* const* d_in, const int* in_sizes, int n_in,
                              void* d_out, int out_size)
{
    (void)in_sizes; (void)n_in;
    const float* key   = (const float*)d_in[0];
    const float* value = (const float*)d_in[1];
    const float* query = (const float*)d_in[2];
    const float* Wq    = (const float*)d_in[3];
    const float* bq    = (const float*)d_in[4];
    const float* Wk    = (const float*)d_in[5];
    const float* bk    = (const float*)d_in[6];
    const float* Wv    = (const float*)d_in[7];
    const float* bv    = (const float*)d_in[8];
    const float* gamma = (const float*)d_in[9];
    const float* beta  = (const float*)d_in[10];

    float* out = (float*)d_out;
    const long long OUT_ELEMS  = (long long)M_QKV * DIM;                 // 4,194,304
    const long long ATTN_ELEMS = (long long)NHEADS * SEQ * SEQ;          // 67,108,864
    // attn goes into d_out right after `output` when the harness grades both.
    float* attn_ext = ((long long)out_size >= OUT_ELEMS + ATTN_ELEMS)
                          ? (out + OUT_ELEMS) : nullptr;

    dim3 g1(DIM / 128, M_QKV / 128, 3);          // (8, 32, 3)
    qkv_kernel<<<g1, 256>>>(query, key, value, Wq, Wk, Wv, bq, bk, bv);

    dim3 g2(SEQ / 128, SEQ / 128, NHEADS);       // (8, 8, 64)
    scores_kernel<<<g2, 256>>>(attn_ext);

    softmax_kernel<<<NHEADS * SEQ, 256>>>(attn_ext);   // 65536 rows

    dim3 g4(1, SEQ / 128, NHEADS);               // (1, 8, 64)
    pv_kernel<<<g4, 256>>>(attn_ext);

    ln_kernel<<<M_QKV, 256>>>(query, gamma, beta, out);
}

// round 4
// speedup vs baseline: 2.0704x; 2.0704x over previous
#include <cuda_runtime.h>
#include <math.h>
#include <stdint.h>

// B=4, S=1024, D=1024, H=16, DH=64 -> BH=64 heads, per-head Q/K/V = [1024,64] contiguous
#define M_QKV   4096
#define DIM     1024
#define NHEADS  64
#define SEQ     1024
#define HDIM    64
#define SCALE   0.03125f      // D^-0.5
#define LN_EPS  1e-5f

#define SSTR    20            // smem row stride (floats) for [rows][16] tiles: conflict-free
#define VSTR    72            // smem row stride for V tile [16][64]: conflict-free frag loads

// -------------------- scratch (allocation-free: __device__ globals) --------------------
__device__ float g_q[M_QKV * DIM];
__device__ float g_k[M_QKV * DIM];
__device__ float g_v[M_QKV * DIM];
__device__ float g_ctx[M_QKV * DIM];
__device__ float g_attn[(size_t)NHEADS * SEQ * SEQ];

// -------------------- tf32 helpers --------------------
__device__ __forceinline__ float to_tf32(float x) {
    uint32_t u;
    asm("cvt.rna.tf32.f32 %0, %1;" : "=r"(u) : "f"(x));
    return __uint_as_float(u);
}

__device__ __forceinline__ void mma_tf32(float (&d)[4], const float (&a)[4], const float (&b)[2]) {
    asm volatile(
        "mma.sync.aligned.m16n8k8.row.col.f32.tf32.tf32.f32 "
        "{%0,%1,%2,%3}, {%4,%5,%6,%7}, {%8,%9}, {%0,%1,%2,%3};\n"
        : "+f"(d[0]), "+f"(d[1]), "+f"(d[2]), "+f"(d[3])
        : "r"(__float_as_uint(a[0])), "r"(__float_as_uint(a[1])),
          "r"(__float_as_uint(a[2])), "r"(__float_as_uint(a[3])),
          "r"(__float_as_uint(b[0])), "r"(__float_as_uint(b[1])));
}

// ============================================================================
// Kernel 1: QKV projections on tensor cores (tf32).
// C[m,n] = sum_k A[m,k]*W[n,k] + b[n].  128x128x16 tile, 256 thr, 8 warps 4x2.
// ============================================================================
__global__ __launch_bounds__(256, 2)
void qkv_tc(const float* __restrict__ Xq, const float* __restrict__ Xk, const float* __restrict__ Xv,
            const float* __restrict__ Wq, const float* __restrict__ Wk, const float* __restrict__ Wv,
            const float* __restrict__ bq, const float* __restrict__ bk, const float* __restrict__ bv)
{
    __shared__ float As[128 * SSTR];
    __shared__ float Bs[128 * SSTR];

    const int z = blockIdx.z;
    const float* A    = (z == 0) ? Xq : (z == 1) ? Xk : Xv;
    const float* W    = (z == 0) ? Wq : (z == 1) ? Wk : Wv;
    const float* bias = (z == 0) ? bq : (z == 1) ? bk : bv;
    float*       C    = (z == 0) ? g_q : (z == 1) ? g_k : g_v;

    const int tid  = threadIdx.x;
    const int lane = tid & 31;
    const int warp = tid >> 5;
    const int g    = lane >> 2;       // group id 0..7
    const int tg   = lane & 3;        // thread in group 0..3
    const int wm   = (warp >> 1) * 32;
    const int wn   = (warp & 1) * 64;
    const int m0   = blockIdx.y * 128;
    const int n0   = blockIdx.x * 128;
    const int lr   = tid >> 2;        // 0..63
    const int lc   = (tid & 3) * 4;   // 0,4,8,12

    const float* Ap  = A + (size_t)(m0 + lr) * DIM + lc;
    const float* Ap2 = A + (size_t)(m0 + lr + 64) * DIM + lc;
    const float* Wp  = W + (size_t)(n0 + lr) * DIM + lc;
    const float* Wp2 = W + (size_t)(n0 + lr + 64) * DIM + lc;

    float acc[2][8][4];
#pragma unroll
    for (int i = 0; i < 2; i++)
#pragma unroll
        for (int j = 0; j < 8; j++)
#pragma unroll
            for (int q = 0; q < 4; q++) acc[i][j][q] = 0.f;

    float4 ra0 = *(const float4*)(Ap);
    float4 ra1 = *(const float4*)(Ap2);
    float4 rb0 = *(const float4*)(Wp);
    float4 rb1 = *(const float4*)(Wp2);

    for (int k0 = 0; k0 < DIM; k0 += 16) {
        float* as  = &As[lr * SSTR + lc];
        float* as2 = &As[(lr + 64) * SSTR + lc];
        float* bs  = &Bs[lr * SSTR + lc];
        float* bs2 = &Bs[(lr + 64) * SSTR + lc];
        as[0]  = to_tf32(ra0.x); as[1]  = to_tf32(ra0.y); as[2]  = to_tf32(ra0.z); as[3]  = to_tf32(ra0.w);
        as2[0] = to_tf32(ra1.x); as2[1] = to_tf32(ra1.y); as2[2] = to_tf32(ra1.z); as2[3] = to_tf32(ra1.w);
        bs[0]  = to_tf32(rb0.x); bs[1]  = to_tf32(rb0.y); bs[2]  = to_tf32(rb0.z); bs[3]  = to_tf32(rb0.w);
        bs2[0] = to_tf32(rb1.x); bs2[1] = to_tf32(rb1.y); bs2[2] = to_tf32(rb1.z); bs2[3] = to_tf32(rb1.w);
        __syncthreads();

        if (k0 + 16 < DIM) {
            ra0 = *(const float4*)(Ap  + k0 + 16);
            ra1 = *(const float4*)(Ap2 + k0 + 16);
            rb0 = *(const float4*)(Wp  + k0 + 16);
            rb1 = *(const float4*)(Wp2 + k0 + 16);
        }

#pragma unroll
        for (int ks = 0; ks < 2; ks++) {
            const int kb = ks * 8;
            float af[2][4];
#pragma unroll
            for (int mt = 0; mt < 2; mt++) {
                const int rb = wm + mt * 16;
                af[mt][0] = As[(rb + g) * SSTR + kb + tg];
                af[mt][1] = As[(rb + g + 8) * SSTR + kb + tg];
                af[mt][2] = As[(rb + g) * SSTR + kb + tg + 4];
                af[mt][3] = As[(rb + g + 8) * SSTR + kb + tg + 4];
            }
            float bf[8][2];
#pragma unroll
            for (int nt = 0; nt < 8; nt++) {
                const int cb = wn + nt * 8;
                bf[nt][0] = Bs[(cb + g) * SSTR + kb + tg];
                bf[nt][1] = Bs[(cb + g) * SSTR + kb + tg + 4];
            }
#pragma unroll
            for (int mt = 0; mt < 2; mt++)
#pragma unroll
                for (int nt = 0; nt < 8; nt++)
                    mma_tf32(acc[mt][nt], af[mt], bf[nt]);
        }
        __syncthreads();
    }

#pragma unroll
    for (int mt = 0; mt < 2; mt++)
#pragma unroll
        for (int nt = 0; nt < 8; nt++) {
            const int row = m0 + wm + mt * 16 + g;
            const int col = n0 + wn + nt * 8 + 2 * tg;
            const float bx = bias[col], by = bias[col + 1];
            float2 o0 = make_float2(acc[mt][nt][0] + bx, acc[mt][nt][1] + by);
            float2 o1 = make_float2(acc[mt][nt][2] + bx, acc[mt][nt][3] + by);
            *(float2*)&C[(size_t)row * DIM + col]       = o0;
            *(float2*)&C[(size_t)(row + 8) * DIM + col] = o1;
        }
}

// ============================================================================
// Kernel 2: scores = scale * Q K^T per head, tf32 tensor cores.
// M=N=1024, K=64.  Same tile as qkv with lda=ldb=64.
// ============================================================================
__global__ __launch_bounds__(256, 2)
void scores_tc(float* attn_ext)
{
    float* attn = attn_ext ? attn_ext : g_attn;

    __shared__ float As[128 * SSTR];
    __shared__ float Bs[128 * SSTR];

    const int bh = blockIdx.z;
    const float* Q = g_q + (size_t)bh * SEQ * HDIM;
    const float* K = g_k + (size_t)bh * SEQ * HDIM;
    float*       C = attn + (size_t)bh * SEQ * SEQ;

    const int tid  = threadIdx.x;
    const int lane = tid & 31;
    const int warp = tid >> 5;
    const int g    = lane >> 2;
    const int tg   = lane & 3;
    const int wm   = (warp >> 1) * 32;
    const int wn   = (warp & 1) * 64;
    const int m0   = blockIdx.y * 128;
    const int n0   = blockIdx.x * 128;
    const int lr   = tid >> 2;
    const int lc   = (tid & 3) * 4;

    const float* Qp  = Q + (size_t)(m0 + lr) * HDIM + lc;
    const float* Qp2 = Q + (size_t)(m0 + lr + 64) * HDIM + lc;
    const float* Kp  = K + (size_t)(n0 + lr) * HDIM + lc;
    const float* Kp2 = K + (size_t)(n0 + lr + 64) * HDIM + lc;

    float acc[2][8][4];
#pragma unroll
    for (int i = 0; i < 2; i++)
#pragma unroll
        for (int j = 0; j < 8; j++)
#pragma unroll
            for (int q = 0; q < 4; q++) acc[i][j][q] = 0.f;

    float4 ra0 = *(const float4*)(Qp);
    float4 ra1 = *(const float4*)(Qp2);
    float4 rb0 = *(const float4*)(Kp);
    float4 rb1 = *(const float4*)(Kp2);

    for (int k0 = 0; k0 < HDIM; k0 += 16) {
        float* as  = &As[lr * SSTR + lc];
        float* as2 = &As[(lr + 64) * SSTR + lc];
        float* bs  = &Bs[lr * SSTR + lc];
        float* bs2 = &Bs[(lr + 64) * SSTR + lc];
        as[0]  = to_tf32(ra0.x); as[1]  = to_tf32(ra0.y); as[2]  = to_tf32(ra0.z); as[3]  = to_tf32(ra0.w);
        as2[0] = to_tf32(ra1.x); as2[1] = to_tf32(ra1.y); as2[2] = to_tf32(ra1.z); as2[3] = to_tf32(ra1.w);
        bs[0]  = to_tf32(rb0.x); bs[1]  = to_tf32(rb0.y); bs[2]  = to_tf32(rb0.z); bs[3]  = to_tf32(rb0.w);
        bs2[0] = to_tf32(rb1.x); bs2[1] = to_tf32(rb1.y); bs2[2] = to_tf32(rb1.z); bs2[3] = to_tf32(rb1.w);
        __syncthreads();

        if (k0 + 16 < HDIM) {
            ra0 = *(const float4*)(Qp  + k0 + 16);
            ra1 = *(const float4*)(Qp2 + k0 + 16);
            rb0 = *(const float4*)(Kp  + k0 + 16);
            rb1 = *(const float4*)(Kp2 + k0 + 16);
        }

#pragma unroll
        for (int ks = 0; ks < 2; ks++) {
            const int kb = ks * 8;
            float af[2][4];
#pragma unroll
            for (int mt = 0; mt < 2; mt++) {
                const int rb = wm + mt * 16;
                af[mt][0] = As[(rb + g) * SSTR + kb + tg];
                af[mt][1] = As[(rb + g + 8) * SSTR + kb + tg];
                af[mt][2] = As[(rb + g) * SSTR + kb + tg + 4];
                af[mt][3] = As[(rb + g + 8) * SSTR + kb + tg + 4];
            }
            float bf[8][2];
#pragma unroll
            for (int nt = 0; nt < 8; nt++) {
                const int cb = wn + nt * 8;
                bf[nt][0] = Bs[(cb + g) * SSTR + kb + tg];
                bf[nt][1] = Bs[(cb + g) * SSTR + kb + tg + 4];
            }
#pragma unroll
            for (int mt = 0; mt < 2; mt++)
#pragma unroll
                for (int nt = 0; nt < 8; nt++)
                    mma_tf32(acc[mt][nt], af[mt], bf[nt]);
        }
        __syncthreads();
    }

#pragma unroll
    for (int mt = 0; mt < 2; mt++)
#pragma unroll
        for (int nt = 0; nt < 8; nt++) {
            const int row = m0 + wm + mt * 16 + g;
            const int col = n0 + wn + nt * 8 + 2 * tg;
            float2 o0 = make_float2(acc[mt][nt][0] * SCALE, acc[mt][nt][1] * SCALE);
            float2 o1 = make_float2(acc[mt][nt][2] * SCALE, acc[mt][nt][3] * SCALE);
            *(float2*)&C[(size_t)row * SEQ + col]       = o0;
            *(float2*)&C[(size_t)(row + 8) * SEQ + col] = o1;
        }
}

// ============================================================================
// Kernel 3: row softmax, in place (unchanged from R3 — near memory floor).
// ============================================================================
__global__ __launch_bounds__(256)
void softmax_kernel(float* attn_ext)
{
    float* attn = attn_ext ? attn_ext : g_attn;
    float* row  = attn + (size_t)blockIdx.x * SEQ;
    const int t = threadIdx.x;

    float4 v = *(const float4*)&row[t * 4];

    __shared__ float red[256];
    float lmax = fmaxf(fmaxf(v.x, v.y), fmaxf(v.z, v.w));
    red[t] = lmax;
    __syncthreads();
#pragma unroll
    for (int s = 128; s > 0; s >>= 1) {
        if (t < s) red[t] = fmaxf(red[t], red[t + s]);
        __syncthreads();
    }
    const float mx = red[0];
    __syncthreads();

    float e0 = expf(v.x - mx), e1 = expf(v.y - mx);
    float e2 = expf(v.z - mx), e3 = expf(v.w - mx);
    red[t] = e0 + e1 + e2 + e3;
    __syncthreads();
#pragma unroll
    for (int s = 128; s > 0; s >>= 1) {
        if (t < s) red[t] += red[t + s];
        __syncthreads();
    }
    const float inv = 1.0f / red[0];

    *(float4*)&row[t * 4] = make_float4(e0 * inv, e1 * inv, e2 * inv, e3 * inv);
}

// ============================================================================
// Kernel 4: context = P @ V per head, tf32 tensor cores.
// M=1024, N=64, K=1024.  128x64x16 tile, warps 4x2 (32x32 each).
// ============================================================================
__global__ __launch_bounds__(256, 2)
void pv_tc(const float* attn_ext_c)
{
    const float* attn = attn_ext_c ? attn_ext_c : g_attn;

    __shared__ float Ps[128 * SSTR];
    __shared__ float Vs[16 * VSTR];

    const int bh = blockIdx.z;
    const float* P = attn  + (size_t)bh * SEQ * SEQ;
    const float* V = g_v   + (size_t)bh * SEQ * HDIM;
    float*       C = g_ctx + (size_t)bh * SEQ * HDIM;

    const int tid  = threadIdx.x;
    const int lane = tid & 31;
    const int warp = tid >> 5;
    const int g    = lane >> 2;
    const int tg   = lane & 3;
    const int wm   = (warp >> 1) * 32;
    const int wn   = (warp & 1) * 32;
    const int m0   = blockIdx.y * 128;
    const int lr   = tid >> 2;
    const int lc   = (tid & 3) * 4;
    const int vr   = tid >> 4;        // 0..15
    const int vc   = (tid & 15) * 4;  // 0..60

    const float* Pp  = P + (size_t)(m0 + lr) * SEQ + lc;
    const float* Pp2 = P + (size_t)(m0 + lr + 64) * SEQ + lc;
    const float* Vp  = V + (size_t)vr * HDIM + vc;

    float acc[2][4][4];
#pragma unroll
    for (int i = 0; i < 2; i++)
#pragma unroll
        for (int j = 0; j < 4; j++)
#pragma unroll
            for (int q = 0; q < 4; q++) acc[i][j][q] = 0.f;

    float4 rp0 = *(const float4*)(Pp);
    float4 rp1 = *(const float4*)(Pp2);
    float4 rv  = *(const float4*)(Vp);

    for (int k0 = 0; k0 < SEQ; k0 += 16) {
        float* ps  = &Ps[lr * SSTR + lc];
        float* ps2 = &Ps[(lr + 64) * SSTR + lc];
        float* vs  = &Vs[vr * VSTR + vc];
        ps[0]  = to_tf32(rp0.x); ps[1]  = to_tf32(rp0.y); ps[2]  = to_tf32(rp0.z); ps[3]  = to_tf32(rp0.w);
        ps2[0] = to_tf32(rp1.x); ps2[1] = to_tf32(rp1.y); ps2[2] = to_tf32(rp1.z); ps2[3] = to_tf32(rp1.w);
        vs[0]  = to_tf32(rv.x);  vs[1]  = to_tf32(rv.y);  vs[2]  = to_tf32(rv.z);  vs[3]  = to_tf32(rv.w);
        __syncthreads();

        if (k0 + 16 < SEQ) {
            rp0 = *(const float4*)(Pp  + k0 + 16);
            rp1 = *(const float4*)(Pp2 + k0 + 16);
            rv  = *(const float4*)(Vp + (size_t)(k0 + 16) * HDIM);
        }

#pragma unroll
        for (int ks = 0; ks < 2; ks++) {
            const int kb = ks * 8;
            float af[2][4];
#pragma unroll
            for (int mt = 0; mt < 2; mt++) {
                const int rb = wm + mt * 16;
                af[mt][0] = Ps[(rb + g) * SSTR + kb + tg];
                af[mt][1] = Ps[(rb + g + 8) * SSTR + kb + tg];
                af[mt][2] = Ps[(rb + g) * SSTR + kb + tg + 4];
                af[mt][3] = Ps[(rb + g + 8) * SSTR + kb + tg + 4];
            }
            float bf[4][2];
#pragma unroll
            for (int nt = 0; nt < 4; nt++) {
                const int cb = wn + nt * 8;
                bf[nt][0] = Vs[(kb + tg) * VSTR + cb + g];
                bf[nt][1] = Vs[(kb + tg + 4) * VSTR + cb + g];
            }
#pragma unroll
            for (int mt = 0; mt < 2; mt++)
#pragma unroll
                for (int nt = 0; nt < 4; nt++)
                    mma_tf32(acc[mt][nt], af[mt], bf[nt]);
        }
        __syncthreads();
    }

#pragma unroll
    for (int mt = 0; mt < 2; mt++)
#pragma unroll
        for (int nt = 0; nt < 4; nt++) {
            const int row = m0 + wm + mt * 16 + g;
            const int col = wn + nt * 8 + 2 * tg;
            *(float2*)&C[(size_t)row * HDIM + col]       = make_float2(acc[mt][nt][0], acc[mt][nt][1]);
            *(float2*)&C[(size_t)(row + 8) * HDIM + col] = make_float2(acc[mt][nt][2], acc[mt][nt][3]);
        }
}

// ============================================================================
// Kernel 5: output = LayerNorm(query + context) * gamma + beta (unchanged).
// ============================================================================
__global__ __launch_bounds__(256)
void ln_kernel(const float* __restrict__ query, const float* __restrict__ gamma,
               const float* __restrict__ beta, float* __restrict__ out)
{
    const int row = blockIdx.x;
    const int t   = threadIdx.x;
    const float* qp = query + (size_t)row * DIM;
    const float* cp = g_ctx + (size_t)row * DIM;

    float4 qv = *(const float4*)&qp[t * 4];
    float4 cv = *(const float4*)&cp[t * 4];
    float x0 = qv.x + cv.x, x1 = qv.y + cv.y, x2 = qv.z + cv.z, x3 = qv.w + cv.w;

    __shared__ float red[256];
    red[t] = x0 + x1 + x2 + x3;
    __syncthreads();
#pragma unroll
    for (int s = 128; s > 0; s >>= 1) {
        if (t < s) red[t] += red[t + s];
        __syncthreads();
    }
    const float mu = red[0] * (1.0f / (float)DIM);
    __syncthreads();

    float d0 = x0 - mu, d1 = x1 - mu, d2 = x2 - mu, d3 = x3 - mu;
    red[t] = d0 * d0 + d1 * d1 + d2 * d2 + d3 * d3;
    __syncthreads();
#pragma unroll
    for (int s = 128; s > 0; s >>= 1) {
        if (t < s) red[t] += red[t + s];
        __syncthreads();
    }
    const float rs = rsqrtf(red[0] * (1.0f / (float)DIM) + LN_EPS);

    float4 g4 = *(const float4*)&gamma[t * 4];
    float4 b4 = *(const float4*)&beta[t * 4];
    float4 o  = make_float4(d0 * rs * g4.x + b4.x,
                            d1 * rs * g4.y + b4.y,
                            d2 * rs * g4.z + b4.z,
                            d3 * rs * g4.w + b4.w);
    *(float4*)&out[(size_t)row * DIM + t * 4] = o;
}

// ============================================================================
// Launcher. Inputs: key, value, query, Wq, bq, Wk, bk, Wv, bv, gamma, beta.
// Output tuple: (output[B,S,D], attn[B*H,S,S]) concatenated in d_out.
// ============================================================================
extern "C" void kernel_launch(void* const* d_in, const int* in_sizes, int n_in,
                              void* d_out, int out_size)
{
    (void)in_sizes; (void)n_in;
    const float* key   = (const float*)d_in[0];
    const float* value = (const float*)d_in[1];
    const float* query = (const float*)d_in[2];
    const float* Wq    = (const float*)d_in[3];
    const float* bq    = (const float*)d_in[4];
    const float* Wk    = (const float*)d_in[5];
    const float* bk    = (const float*)d_in[6];
    const float* Wv    = (const float*)d_in[7];
    const float* bv    = (const float*)d_in[8];
    const float* gamma = (const float*)d_in[9];
    const float* beta  = (const float*)d_in[10];

    float* out = (float*)d_out;
    const long long OUT_ELEMS  = (long long)M_QKV * DIM;
    const long long ATTN_ELEMS = (long long)NHEADS * SEQ * SEQ;
    float* attn_ext = ((long long)out_size >= OUT_ELEMS + ATTN_ELEMS)
                          ? (out + OUT_ELEMS) : nullptr;

    dim3 g1(DIM / 128, M_QKV / 128, 3);          // (8, 32, 3)
    qkv_tc<<<g1, 256>>>(query, key, value, Wq, Wk, Wv, bq, bk, bv);

    dim3 g2(SEQ / 128, SEQ / 128, NHEADS);       // (8, 8, 64)
    scores_tc<<<g2, 256>>>(attn_ext);

    softmax_kernel<<<NHEADS * SEQ, 256>>>(attn_ext);

    dim3 g4(1, SEQ / 128, NHEADS);               // (1, 8, 64)
    pv_tc<<<g4, 256>>>(attn_ext);

    ln_kernel<<<M_QKV, 256>>>(query, gamma, beta, out);
}